// round 14
// baseline (speedup 1.0000x reference)
#include <cuda_runtime.h>
#include <cuda_fp16.h>

// Problem constants (fixed by the dataset)
#define N_BATCH 2
#define HW 65536          // 256*256
#define NRAYS 32768       // N_BATCH * 16384
#define RPW 2             // rays per warp
#define RPB 8             // rays per block (4 warps x 2)
#define THREADS 128
#define FPITCH 17         // feats row pitch in u32 (34 halves)

typedef unsigned long long u64;
typedef unsigned int u32;

// channels-last fp16 copy of the planes: [(n*3+p)][hw][c]
__device__ __half g_planesH[(size_t)N_BATCH * 3 * HW * 32];

// ---- dynamic smem layout (bytes) ----
#define SM_W1S    0        // 2048 f32  [c][j]
#define SM_W2RS   8192     // 2048 f32  [j][32 rgb outputs]
#define SM_B1S    16384    // 64 f32
#define SM_W2SIG  16640    // 64 f32
#define SM_B2RS   16896    // 32 f32
#define SM_B2SIG  17024    // 1 f32 (+pad)
#define SM_TAPA   17152    // 4 warps x 32 x 12 int  = 6144
#define SM_TAPW   23296    // 4 warps x 32 x 6 u32   = 3072 (half2 tap weights)
#define SM_FEATS  26368    // 4 warps x 2 rays x 32*34 halves = 17408
#define SM_TOTAL  43776

// ---------- packed f32x2 helpers ----------
__device__ __forceinline__ u64 ffma2(u64 a, u64 b, u64 c) {
    u64 r; asm("fma.rn.f32x2 %0,%1,%2,%3;" : "=l"(r) : "l"(a), "l"(b), "l"(c)); return r;
}
__device__ __forceinline__ u64 pack2(float lo, float hi) {
    u64 r; asm("mov.b64 %0,{%1,%2};" : "=l"(r) : "f"(lo), "f"(hi)); return r;
}
__device__ __forceinline__ void unpack2(u64 d, float& lo, float& hi) {
    asm("mov.b64 {%0,%1},%2;" : "=f"(lo), "=f"(hi) : "l"(d));
}
__device__ __forceinline__ float softplus_f(float x) {
    return fmaxf(x, 0.f) + __logf(1.f + __expf(-fabsf(x)));
}

// ---------- kernel 0: [np][C][HW] f32 -> [np][HW][C] fp16 transpose ----------
__global__ void transpose_kernel(const float* __restrict__ in) {
    __shared__ float tile[32][33];
    int np  = blockIdx.y;
    int hw0 = blockIdx.x * 32;
    int tx = threadIdx.x, ty = threadIdx.y;
#pragma unroll
    for (int i = 0; i < 4; i++) {
        int cc = ty * 4 + i;
        tile[cc][tx] = in[(np * 32 + cc) * HW + hw0 + tx];
    }
    __syncthreads();
#pragma unroll
    for (int i = 0; i < 4; i++) {
        int row = ty * 4 + i;
        g_planesH[(size_t)(np * HW + hw0 + row) * 32 + tx] = __float2half(tile[tx][row]);
    }
}

// ---------- kernel 1: renderer, one warp per 2 rays, 5 blocks/SM ----------
__global__ __launch_bounds__(THREADS, 5) void render_kernel(
    const float* __restrict__ orig, const float* __restrict__ dirs,
    const float* __restrict__ w1, const float* __restrict__ b1,
    const float* __restrict__ w2, const float* __restrict__ b2,
    float* __restrict__ out)
{
    extern __shared__ __align__(16) unsigned char smem[];
    float* w1s    = (float*)(smem + SM_W1S);
    float* w2rs   = (float*)(smem + SM_W2RS);
    float* b1s    = (float*)(smem + SM_B1S);
    float* w2sigs = (float*)(smem + SM_W2SIG);
    float* b2rs   = (float*)(smem + SM_B2RS);
    float* b2sigp = (float*)(smem + SM_B2SIG);
    int*   tapa   = (int*)(smem + SM_TAPA);
    u32*   tapw   = (u32*)(smem + SM_TAPW);
    u32*   featsb = (u32*)(smem + SM_FEATS);   // half2 lattice, pitch FPITCH u32

    const int tid = threadIdx.x;
    for (int i = tid; i < 2048; i += THREADS) w1s[i] = w1[i];
    if (tid < 64) b1s[tid] = b1[tid];
    for (int i = tid; i < 64 * 33; i += THREADS) {
        int j = i / 33, k = i - j * 33;
        float v = w2[i];
        if (k == 0) w2sigs[j] = v; else w2rs[j * 32 + (k - 1)] = v;
    }
    if (tid < 32) b2rs[tid] = b2[tid + 1];
    if (tid == 0) b2sigp[0] = b2[0];
    __syncthreads();

    const int w = tid >> 5, lane = tid & 31;
    const int rg0 = blockIdx.x * RPB + w * RPW;   // first ray of this warp
    const unsigned FULL = 0xffffffffu;

    const float t   = (lane + 0.5f) * 0.03125f;
    const float dep = 2.25f + 1.05f * t;

    // ---- stage 1+2 per ray: taps (lane = sample), then half2 gather ----
#pragma unroll
    for (int r = 0; r < RPW; r++) {
        const int rg = rg0 + r;
        const int n  = rg >> 14;
        const float ox = orig[rg * 3 + 0], oy = orig[rg * 3 + 1], oz = orig[rg * 3 + 2];
        const float dx = dirs[rg * 3 + 0], dy = dirs[rg * 3 + 1], dz = dirs[rg * 3 + 2];
        const float cx = 2.f * fmaf(dep, dx, ox);
        const float cy = 2.f * fmaf(dep, dy, oy);
        const float cz = 2.f * fmaf(dep, dz, oz);

        const int so = w * 32 + lane;   // sample slot for stage-1 writes
#pragma unroll
        for (int p = 0; p < 3; p++) {
            float u = (p == 0) ? cx : (p == 1) ? cy : cx;
            float v = (p == 0) ? cy : (p == 1) ? cz : cz;
            float ix = ((u + 1.f) * 0.5f) * 255.f;
            float iy = ((v + 1.f) * 0.5f) * 255.f;
            float fx0 = floorf(ix), fy0 = floorf(iy);
            // fold the 1/3 plane-mean into the x-weights
            float a0 = (ix - fx0) * (1.f / 3.f);
            float a1 = ((fx0 + 1.f) - ix) * (1.f / 3.f);
            float bb0 = iy - fy0, bb1 = (fy0 + 1.f) - iy;
            int ix0 = (int)fminf(fmaxf(fx0, 0.f), 255.f);
            int ix1 = (int)fminf(fmaxf(fx0 + 1.f, 0.f), 255.f);
            int iy0 = (int)fminf(fmaxf(fy0, 0.f), 255.f);
            int iy1 = (int)fminf(fmaxf(fy0 + 1.f, 0.f), 255.f);
            int base = (n * 3 + p) * (HW * 32);
            int r0 = base + iy0 * (256 * 32);
            int r1 = base + iy1 * (256 * 32);
            *(int4*)&tapa[so * 12 + p * 4] =
                make_int4(r0 + ix0 * 32, r0 + ix1 * 32, r1 + ix0 * 32, r1 + ix1 * 32);
            __half2 hw0 = __floats2half2_rn(a1 * bb1, a0 * bb1);
            __half2 hw1 = __floats2half2_rn(a1 * bb0, a0 * bb0);
            uint2 st;
            st.x = *reinterpret_cast<u32*>(&hw0);
            st.y = *reinterpret_cast<u32*>(&hw1);
            *(uint2*)&tapw[so * 6 + p * 2] = st;
        }
        __syncwarp();

        // gather: lanes = 4 channel-octets x 8 samples; each lane privately
        // accumulates its sample's 12 taps for 8 channels in half2 (HFMA2).
        {
            const int q4   = lane & 3;            // channel octet
            const int sub  = lane >> 2;           // sample sub-index (0..7)
            const int cpos = q4 * 8;
            u32* feats = featsb + (w * 2 + r) * (32 * FPITCH);
#pragma unroll 2
            for (int sb = 0; sb < 32; sb += 8) {
                const int s = sb + sub;
                const int* ta = tapa + (w * 32 + s) * 12;
                const u32* tw = tapw + (w * 32 + s) * 6;
                int4 A = *(const int4*)ta;
                int4 B = *(const int4*)(ta + 4);
                int4 C = *(const int4*)(ta + 8);
                uint2 W01 = *(const uint2*)tw;
                uint2 W23 = *(const uint2*)(tw + 2);
                uint2 W45 = *(const uint2*)(tw + 4);
                int addr[12] = {A.x, A.y, A.z, A.w, B.x, B.y, B.z, B.w,
                                C.x, C.y, C.z, C.w};
                u32 wb[6] = {W01.x, W01.y, W23.x, W23.y, W45.x, W45.y};
                __half2 ac0 = __float2half2_rn(0.f);
                __half2 ac1 = ac0, ac2 = ac0, ac3 = ac0;
#pragma unroll
                for (int tp = 0; tp < 12; tp++) {
                    __half2 hp = *reinterpret_cast<__half2*>(&wb[tp >> 1]);
                    __half2 wh = (tp & 1) ? __high2half2(hp) : __low2half2(hp);
                    uint4 raw = *(const uint4*)&g_planesH[addr[tp] + cpos];
                    ac0 = __hfma2(wh, *reinterpret_cast<__half2*>(&raw.x), ac0);
                    ac1 = __hfma2(wh, *reinterpret_cast<__half2*>(&raw.y), ac1);
                    ac2 = __hfma2(wh, *reinterpret_cast<__half2*>(&raw.z), ac2);
                    ac3 = __hfma2(wh, *reinterpret_cast<__half2*>(&raw.w), ac3);
                }
                u32* f = feats + s * FPITCH + q4 * 4;
                f[0] = *reinterpret_cast<u32*>(&ac0);
                f[1] = *reinterpret_cast<u32*>(&ac1);
                f[2] = *reinterpret_cast<u32*>(&ac2);
                f[3] = *reinterpret_cast<u32*>(&ac3);
            }
        }
        __syncwarp();
    }

    // ---- MLP for both samples (lane's sample of ray0 and ray1) ----
    const u32* frow0 = featsb + (w * 2 + 0) * (32 * FPITCH) + lane * FPITCH;
    const u32* frow1 = featsb + (w * 2 + 1) * (32 * FPITCH) + lane * FPITCH;

    const float b2sig = b2sigp[0];
    float sig0 = b2sig, sig1 = b2sig;
    u64 a20[16], a21[16];
    const u64* b2d = (const u64*)b2rs;
#pragma unroll
    for (int k = 0; k < 16; k++) { a20[k] = b2d[k]; a21[k] = b2d[k]; }

    const ulonglong2* w1d2 = (const ulonglong2*)w1s;
    const ulonglong2* w2d2 = (const ulonglong2*)w2rs;
    const u64* b1d = (const u64*)b1s;

#pragma unroll 1
    for (int q = 0; q < 8; q++) {       // 8 hidden units per pass (regs!)
        u64 ac0[4], ac1[4];
#pragma unroll
        for (int jp = 0; jp < 4; jp++) { ac0[jp] = b1d[q * 4 + jp]; ac1[jp] = ac0[jp]; }

#pragma unroll 4
        for (int c2 = 0; c2 < 16; c2++) {      // channel pairs
            u32 r0b = frow0[c2], r1b = frow1[c2];
            float2 f0 = __half22float2(*reinterpret_cast<__half2*>(&r0b));
            float2 f1 = __half22float2(*reinterpret_cast<__half2*>(&r1b));
#pragma unroll
            for (int e = 0; e < 2; e++) {
                float fe0 = (e == 0) ? f0.x : f0.y;
                float fe1 = (e == 0) ? f1.x : f1.y;
                u64 f02 = pack2(fe0, fe0), f12 = pack2(fe1, fe1);
                const ulonglong2* wr = w1d2 + (2 * c2 + e) * 16 + q * 2;
#pragma unroll
                for (int jq = 0; jq < 2; jq++) {
                    ulonglong2 ww = wr[jq];
                    ac0[2 * jq]     = ffma2(f02, ww.x, ac0[2 * jq]);
                    ac0[2 * jq + 1] = ffma2(f02, ww.y, ac0[2 * jq + 1]);
                    ac1[2 * jq]     = ffma2(f12, ww.x, ac1[2 * jq]);
                    ac1[2 * jq + 1] = ffma2(f12, ww.y, ac1[2 * jq + 1]);
                }
            }
        }
        // consume the 8 hidden units of this pass into layer 2
#pragma unroll
        for (int jp = 0; jp < 4; jp++) {
            int j0 = q * 8 + 2 * jp;
            float l0, h0, l1, h1;
            unpack2(ac0[jp], l0, h0);
            unpack2(ac1[jp], l1, h1);
            float h00 = softplus_f(l0), h01 = softplus_f(h0);
            float h10 = softplus_f(l1), h11 = softplus_f(h1);
            float ws0 = w2sigs[j0], ws1 = w2sigs[j0 + 1];
            sig0 = fmaf(h00, ws0, sig0); sig0 = fmaf(h01, ws1, sig0);
            sig1 = fmaf(h10, ws0, sig1); sig1 = fmaf(h11, ws1, sig1);
            u64 p00 = pack2(h00, h00), p01 = pack2(h01, h01);
            u64 p10 = pack2(h10, h10), p11 = pack2(h11, h11);
            const ulonglong2* wr0 = w2d2 + j0 * 8;
#pragma unroll
            for (int kq = 0; kq < 8; kq++) {
                ulonglong2 ww0 = wr0[kq];
                ulonglong2 ww1 = wr0[8 + kq];
                u64 v0 = ffma2(p00, ww0.x, a20[2 * kq]);
                u64 v1 = ffma2(p00, ww0.y, a20[2 * kq + 1]);
                a20[2 * kq]     = ffma2(p01, ww1.x, v0);
                a20[2 * kq + 1] = ffma2(p01, ww1.y, v1);
                u64 u0 = ffma2(p10, ww0.x, a21[2 * kq]);
                u64 u1 = ffma2(p10, ww0.y, a21[2 * kq + 1]);
                a21[2 * kq]     = ffma2(p11, ww1.x, u0);
                a21[2 * kq + 1] = ffma2(p11, ww1.y, u1);
            }
        }
    }

    // ---- ray marching per ray: warp scan over samples (lane = s) ----
#pragma unroll
    for (int r = 0; r < RPW; r++) {
        float sig = (r == 0) ? sig0 : sig1;
        float rgb[32];
#pragma unroll
        for (int k = 0; k < 16; k++) {
            u64 av = (r == 0) ? a20[k] : a21[k];
            float lo, hi; unpack2(av, lo, hi);
            rgb[2 * k]     = __fdividef(1.002f, 1.f + __expf(-lo)) - 0.001f;
            rgb[2 * k + 1] = __fdividef(1.002f, 1.f + __expf(-hi)) - 0.001f;
        }

        float sig_n = __shfl_down_sync(FULL, sig, 1);
        float dep_n = __shfl_down_sync(FULL, dep, 1);
        float alpha;
        if (lane < 31) {
            float delta = dep_n - dep;
            float dm = 0.5f * (sig + sig_n);
            float dens = softplus_f(dm - 1.f);
            alpha = 1.f - __expf(-delta * dens);
        } else {
            alpha = 0.f;
        }
        float gg = 1.f - alpha + 1e-10f;
        float pscan = gg;
#pragma unroll
        for (int off = 1; off < 32; off <<= 1) {
            float v = __shfl_up_sync(FULL, pscan, off);
            if (lane >= off) pscan *= v;
        }
        float T = __shfl_up_sync(FULL, pscan, 1);
        if (lane == 0) T = 1.f;
        float wgt = alpha * T;
        float wprev = __shfl_up_sync(FULL, wgt, 1);
        if (lane == 0) wprev = 0.f;
        float coeff = 0.5f * (wgt + wprev);

#pragma unroll
        for (int k = 0; k < 32; k++) rgb[k] *= coeff;
#pragma unroll
        for (int off = 16; off >= 1; off >>= 1) {
#pragma unroll
            for (int k = 0; k < 32; k++) rgb[k] += __shfl_xor_sync(FULL, rgb[k], off);
        }
        if (lane == 0) {
            float4* o4 = (float4*)(out + (rg0 + r) * 32);
#pragma unroll
            for (int k = 0; k < 8; k++)
                o4[k] = make_float4(rgb[4 * k], rgb[4 * k + 1], rgb[4 * k + 2], rgb[4 * k + 3]);
        }
    }
}

extern "C" void kernel_launch(void* const* d_in, const int* in_sizes, int n_in,
                              void* d_out, int out_size) {
    const float* vol  = (const float*)d_in[0];  // [2,3,32,256,256]
    const float* orig = (const float*)d_in[1];  // [2,16384,3]
    const float* dirs = (const float*)d_in[2];  // [2,16384,3]
    const float* w1   = (const float*)d_in[3];  // [32,64]
    const float* b1   = (const float*)d_in[4];  // [64]
    const float* w2   = (const float*)d_in[5];  // [64,33]
    const float* b2   = (const float*)d_in[6];  // [33]
    float* out = (float*)d_out;

    static int inited = 0;
    if (!inited) {
        cudaFuncSetAttribute(render_kernel,
                             cudaFuncAttributeMaxDynamicSharedMemorySize, SM_TOTAL);
        inited = 1;
    }

    dim3 tb(32, 8);
    dim3 tg(HW / 32, N_BATCH * 3);
    transpose_kernel<<<tg, tb>>>(vol);

    render_kernel<<<NRAYS / RPB, THREADS, SM_TOTAL>>>(orig, dirs, w1, b1, w2, b2, out);
}

// round 15
// speedup vs baseline: 1.1118x; 1.1118x over previous
#include <cuda_runtime.h>
#include <cuda_fp16.h>

// Problem constants (fixed by the dataset)
#define N_BATCH 2
#define HW 65536          // 256*256
#define NRAYS 32768       // N_BATCH * 16384
#define RPW 2             // rays per warp
#define RPB 8             // rays per block (4 warps x 2)
#define THREADS 128
#define FPITCH 17         // feats row pitch in u32 (34 halves)

typedef unsigned long long u64;
typedef unsigned int u32;

// channels-last fp16 copy of the planes: [(n*3+p)][hw][c]
__device__ __half g_planesH[(size_t)N_BATCH * 3 * HW * 32];

// ---- dynamic smem layout (bytes) ----
#define SM_W1S    0        // 2048 f32  [c][j]
#define SM_W2RS   8192     // 2048 f32  [j][32 rgb outputs]
#define SM_B1S    16384    // 64 f32
#define SM_W2SIG  16640    // 64 f32
#define SM_B2RS   16896    // 32 f32
#define SM_B2SIG  17024    // 1 f32 (+pad)
#define SM_TAPA   17152    // 4 warps x 32 x 12 int  = 6144
#define SM_TAPW   23296    // 4 warps x 32 x 6 u32   = 3072 (half2 tap weights)
#define SM_FEATS  26368    // 4 warps x 2 rays x 32*34 halves = 17408
#define SM_TOTAL  43776

// ---------- packed f32x2 helpers ----------
__device__ __forceinline__ u64 ffma2(u64 a, u64 b, u64 c) {
    u64 r; asm("fma.rn.f32x2 %0,%1,%2,%3;" : "=l"(r) : "l"(a), "l"(b), "l"(c)); return r;
}
__device__ __forceinline__ u64 pack2(float lo, float hi) {
    u64 r; asm("mov.b64 %0,{%1,%2};" : "=l"(r) : "f"(lo), "f"(hi)); return r;
}
__device__ __forceinline__ void unpack2(u64 d, float& lo, float& hi) {
    asm("mov.b64 {%0,%1},%2;" : "=f"(lo), "=f"(hi) : "l"(d));
}
__device__ __forceinline__ float softplus_f(float x) {
    return fmaxf(x, 0.f) + __logf(1.f + __expf(-fabsf(x)));
}

// ---------- kernel 0: [np][C][HW] f32 -> [np][HW][C] fp16 transpose ----------
__global__ void transpose_kernel(const float* __restrict__ in) {
    __shared__ float tile[32][33];
    int np  = blockIdx.y;
    int hw0 = blockIdx.x * 32;
    int tx = threadIdx.x, ty = threadIdx.y;
#pragma unroll
    for (int i = 0; i < 4; i++) {
        int cc = ty * 4 + i;
        tile[cc][tx] = in[(np * 32 + cc) * HW + hw0 + tx];
    }
    __syncthreads();
#pragma unroll
    for (int i = 0; i < 4; i++) {
        int row = ty * 4 + i;
        g_planesH[(size_t)(np * HW + hw0 + row) * 32 + tx] = __float2half(tile[tx][row]);
    }
}

// ---------- kernel 1: renderer, one warp per 2 rays, 4 blocks/SM ----------
__global__ __launch_bounds__(THREADS, 4) void render_kernel(
    const float* __restrict__ orig, const float* __restrict__ dirs,
    const float* __restrict__ w1, const float* __restrict__ b1,
    const float* __restrict__ w2, const float* __restrict__ b2,
    float* __restrict__ out)
{
    extern __shared__ __align__(16) unsigned char smem[];
    float* w1s    = (float*)(smem + SM_W1S);
    float* w2rs   = (float*)(smem + SM_W2RS);
    float* b1s    = (float*)(smem + SM_B1S);
    float* w2sigs = (float*)(smem + SM_W2SIG);
    float* b2rs   = (float*)(smem + SM_B2RS);
    float* b2sigp = (float*)(smem + SM_B2SIG);
    int*   tapa   = (int*)(smem + SM_TAPA);
    u32*   tapw   = (u32*)(smem + SM_TAPW);
    u32*   featsb = (u32*)(smem + SM_FEATS);   // half2 lattice, pitch FPITCH u32

    const int tid = threadIdx.x;
    for (int i = tid; i < 2048; i += THREADS) w1s[i] = w1[i];
    if (tid < 64) b1s[tid] = b1[tid];
    for (int i = tid; i < 64 * 33; i += THREADS) {
        int j = i / 33, k = i - j * 33;
        float v = w2[i];
        if (k == 0) w2sigs[j] = v; else w2rs[j * 32 + (k - 1)] = v;
    }
    if (tid < 32) b2rs[tid] = b2[tid + 1];
    if (tid == 0) b2sigp[0] = b2[0];
    __syncthreads();

    const int w = tid >> 5, lane = tid & 31;
    const int rg0 = blockIdx.x * RPB + w * RPW;   // first ray of this warp
    const unsigned FULL = 0xffffffffu;

    const float t   = (lane + 0.5f) * 0.03125f;
    const float dep = 2.25f + 1.05f * t;

    // ---- stage 1+2 per ray: taps (lane = sample), then half2 gather ----
#pragma unroll
    for (int r = 0; r < RPW; r++) {
        const int rg = rg0 + r;
        const int n  = rg >> 14;
        const float ox = orig[rg * 3 + 0], oy = orig[rg * 3 + 1], oz = orig[rg * 3 + 2];
        const float dx = dirs[rg * 3 + 0], dy = dirs[rg * 3 + 1], dz = dirs[rg * 3 + 2];
        const float cx = 2.f * fmaf(dep, dx, ox);
        const float cy = 2.f * fmaf(dep, dy, oy);
        const float cz = 2.f * fmaf(dep, dz, oz);

        const int so = w * 32 + lane;   // sample slot for stage-1 writes
#pragma unroll
        for (int p = 0; p < 3; p++) {
            float u = (p == 0) ? cx : (p == 1) ? cy : cx;
            float v = (p == 0) ? cy : (p == 1) ? cz : cz;
            float ix = ((u + 1.f) * 0.5f) * 255.f;
            float iy = ((v + 1.f) * 0.5f) * 255.f;
            float fx0 = floorf(ix), fy0 = floorf(iy);
            // fold the 1/3 plane-mean into the x-weights
            float a0 = (ix - fx0) * (1.f / 3.f);
            float a1 = ((fx0 + 1.f) - ix) * (1.f / 3.f);
            float bb0 = iy - fy0, bb1 = (fy0 + 1.f) - iy;
            int ix0 = (int)fminf(fmaxf(fx0, 0.f), 255.f);
            int ix1 = (int)fminf(fmaxf(fx0 + 1.f, 0.f), 255.f);
            int iy0 = (int)fminf(fmaxf(fy0, 0.f), 255.f);
            int iy1 = (int)fminf(fmaxf(fy0 + 1.f, 0.f), 255.f);
            int base = (n * 3 + p) * (HW * 32);
            int r0 = base + iy0 * (256 * 32);
            int r1 = base + iy1 * (256 * 32);
            *(int4*)&tapa[so * 12 + p * 4] =
                make_int4(r0 + ix0 * 32, r0 + ix1 * 32, r1 + ix0 * 32, r1 + ix1 * 32);
            __half2 hw0 = __floats2half2_rn(a1 * bb1, a0 * bb1);
            __half2 hw1 = __floats2half2_rn(a1 * bb0, a0 * bb0);
            uint2 st;
            st.x = *reinterpret_cast<u32*>(&hw0);
            st.y = *reinterpret_cast<u32*>(&hw1);
            *(uint2*)&tapw[so * 6 + p * 2] = st;
        }
        __syncwarp();

        // gather: lanes = 4 channel-octets x 8 samples; each lane privately
        // accumulates its sample's 12 taps for 8 channels in half2 (HFMA2).
        {
            const int q4   = lane & 3;            // channel octet
            const int sub  = lane >> 2;           // sample sub-index (0..7)
            const int cpos = q4 * 8;
            u32* feats = featsb + (w * 2 + r) * (32 * FPITCH);
#pragma unroll 2
            for (int sb = 0; sb < 32; sb += 8) {
                const int s = sb + sub;
                const int* ta = tapa + (w * 32 + s) * 12;
                const u32* tw = tapw + (w * 32 + s) * 6;
                int4 A = *(const int4*)ta;
                int4 B = *(const int4*)(ta + 4);
                int4 C = *(const int4*)(ta + 8);
                uint2 W01 = *(const uint2*)tw;
                uint2 W23 = *(const uint2*)(tw + 2);
                uint2 W45 = *(const uint2*)(tw + 4);
                int addr[12] = {A.x, A.y, A.z, A.w, B.x, B.y, B.z, B.w,
                                C.x, C.y, C.z, C.w};
                u32 wb[6] = {W01.x, W01.y, W23.x, W23.y, W45.x, W45.y};
                __half2 ac0 = __float2half2_rn(0.f);
                __half2 ac1 = ac0, ac2 = ac0, ac3 = ac0;
#pragma unroll
                for (int tp = 0; tp < 12; tp++) {
                    __half2 hp = *reinterpret_cast<__half2*>(&wb[tp >> 1]);
                    __half2 wh = (tp & 1) ? __high2half2(hp) : __low2half2(hp);
                    uint4 raw = *(const uint4*)&g_planesH[addr[tp] + cpos];
                    ac0 = __hfma2(wh, *reinterpret_cast<__half2*>(&raw.x), ac0);
                    ac1 = __hfma2(wh, *reinterpret_cast<__half2*>(&raw.y), ac1);
                    ac2 = __hfma2(wh, *reinterpret_cast<__half2*>(&raw.z), ac2);
                    ac3 = __hfma2(wh, *reinterpret_cast<__half2*>(&raw.w), ac3);
                }
                u32* f = feats + s * FPITCH + q4 * 4;
                f[0] = *reinterpret_cast<u32*>(&ac0);
                f[1] = *reinterpret_cast<u32*>(&ac1);
                f[2] = *reinterpret_cast<u32*>(&ac2);
                f[3] = *reinterpret_cast<u32*>(&ac3);
            }
        }
        __syncwarp();
    }

    // ---- MLP for both samples (lane's sample of ray0 and ray1) ----
    const u32* frow0 = featsb + (w * 2 + 0) * (32 * FPITCH) + lane * FPITCH;
    const u32* frow1 = featsb + (w * 2 + 1) * (32 * FPITCH) + lane * FPITCH;

    const float b2sig = b2sigp[0];
    float sig0 = b2sig, sig1 = b2sig;
    u64 a20[16], a21[16];
    const u64* b2d = (const u64*)b2rs;
#pragma unroll
    for (int k = 0; k < 16; k++) { a20[k] = b2d[k]; a21[k] = b2d[k]; }

    const ulonglong2* w1d2 = (const ulonglong2*)w1s;
    const ulonglong2* w2d2 = (const ulonglong2*)w2rs;
    const u64* b1d = (const u64*)b1s;

#pragma unroll
    for (int q = 0; q < 4; q++) {       // 16 hidden units per quarter
        u64 ac0[8], ac1[8];
#pragma unroll
        for (int jp = 0; jp < 8; jp++) { ac0[jp] = b1d[q * 8 + jp]; ac1[jp] = ac0[jp]; }

#pragma unroll 4
        for (int c2 = 0; c2 < 16; c2++) {      // channel pairs
            u32 r0b = frow0[c2], r1b = frow1[c2];
            float2 f0 = __half22float2(*reinterpret_cast<__half2*>(&r0b));
            float2 f1 = __half22float2(*reinterpret_cast<__half2*>(&r1b));
#pragma unroll
            for (int e = 0; e < 2; e++) {
                float fe0 = (e == 0) ? f0.x : f0.y;
                float fe1 = (e == 0) ? f1.x : f1.y;
                u64 f02 = pack2(fe0, fe0), f12 = pack2(fe1, fe1);
                const ulonglong2* wr = w1d2 + (2 * c2 + e) * 16 + q * 4;
#pragma unroll
                for (int jq = 0; jq < 4; jq++) {
                    ulonglong2 ww = wr[jq];
                    ac0[2 * jq]     = ffma2(f02, ww.x, ac0[2 * jq]);
                    ac0[2 * jq + 1] = ffma2(f02, ww.y, ac0[2 * jq + 1]);
                    ac1[2 * jq]     = ffma2(f12, ww.x, ac1[2 * jq]);
                    ac1[2 * jq + 1] = ffma2(f12, ww.y, ac1[2 * jq + 1]);
                }
            }
        }
        // consume the 16 hidden units of this quarter into layer 2
#pragma unroll 4
        for (int jp = 0; jp < 8; jp++) {
            int j0 = q * 16 + 2 * jp;
            float l0, h0, l1, h1;
            unpack2(ac0[jp], l0, h0);
            unpack2(ac1[jp], l1, h1);
            float h00 = softplus_f(l0), h01 = softplus_f(h0);
            float h10 = softplus_f(l1), h11 = softplus_f(h1);
            float ws0 = w2sigs[j0], ws1 = w2sigs[j0 + 1];
            sig0 = fmaf(h00, ws0, sig0); sig0 = fmaf(h01, ws1, sig0);
            sig1 = fmaf(h10, ws0, sig1); sig1 = fmaf(h11, ws1, sig1);
            u64 p00 = pack2(h00, h00), p01 = pack2(h01, h01);
            u64 p10 = pack2(h10, h10), p11 = pack2(h11, h11);
            const ulonglong2* wr0 = w2d2 + j0 * 8;
#pragma unroll
            for (int kq = 0; kq < 8; kq++) {
                ulonglong2 ww0 = wr0[kq];
                ulonglong2 ww1 = wr0[8 + kq];
                u64 v0 = ffma2(p00, ww0.x, a20[2 * kq]);
                u64 v1 = ffma2(p00, ww0.y, a20[2 * kq + 1]);
                a20[2 * kq]     = ffma2(p01, ww1.x, v0);
                a20[2 * kq + 1] = ffma2(p01, ww1.y, v1);
                u64 u0 = ffma2(p10, ww0.x, a21[2 * kq]);
                u64 u1 = ffma2(p10, ww0.y, a21[2 * kq + 1]);
                a21[2 * kq]     = ffma2(p11, ww1.x, u0);
                a21[2 * kq + 1] = ffma2(p11, ww1.y, u1);
            }
        }
    }

    // ---- ray marching per ray: warp scan over samples (lane = s) ----
#pragma unroll
    for (int r = 0; r < RPW; r++) {
        float sig = (r == 0) ? sig0 : sig1;
        float rgb[32];
#pragma unroll
        for (int k = 0; k < 16; k++) {
            u64 av = (r == 0) ? a20[k] : a21[k];
            float lo, hi; unpack2(av, lo, hi);
            rgb[2 * k]     = __fdividef(1.002f, 1.f + __expf(-lo)) - 0.001f;
            rgb[2 * k + 1] = __fdividef(1.002f, 1.f + __expf(-hi)) - 0.001f;
        }

        float sig_n = __shfl_down_sync(FULL, sig, 1);
        float dep_n = __shfl_down_sync(FULL, dep, 1);
        float alpha;
        if (lane < 31) {
            float delta = dep_n - dep;
            float dm = 0.5f * (sig + sig_n);
            float dens = softplus_f(dm - 1.f);
            alpha = 1.f - __expf(-delta * dens);
        } else {
            alpha = 0.f;
        }
        float gg = 1.f - alpha + 1e-10f;
        float pscan = gg;
#pragma unroll
        for (int off = 1; off < 32; off <<= 1) {
            float v = __shfl_up_sync(FULL, pscan, off);
            if (lane >= off) pscan *= v;
        }
        float T = __shfl_up_sync(FULL, pscan, 1);
        if (lane == 0) T = 1.f;
        float wgt = alpha * T;
        float wprev = __shfl_up_sync(FULL, wgt, 1);
        if (lane == 0) wprev = 0.f;
        float coeff = 0.5f * (wgt + wprev);

#pragma unroll
        for (int k = 0; k < 32; k++) rgb[k] *= coeff;
#pragma unroll
        for (int off = 16; off >= 1; off >>= 1) {
#pragma unroll
            for (int k = 0; k < 32; k++) rgb[k] += __shfl_xor_sync(FULL, rgb[k], off);
        }
        if (lane == 0) {
            float4* o4 = (float4*)(out + (rg0 + r) * 32);
#pragma unroll
            for (int k = 0; k < 8; k++)
                o4[k] = make_float4(rgb[4 * k], rgb[4 * k + 1], rgb[4 * k + 2], rgb[4 * k + 3]);
        }
    }
}

extern "C" void kernel_launch(void* const* d_in, const int* in_sizes, int n_in,
                              void* d_out, int out_size) {
    const float* vol  = (const float*)d_in[0];  // [2,3,32,256,256]
    const float* orig = (const float*)d_in[1];  // [2,16384,3]
    const float* dirs = (const float*)d_in[2];  // [2,16384,3]
    const float* w1   = (const float*)d_in[3];  // [32,64]
    const float* b1   = (const float*)d_in[4];  // [64]
    const float* w2   = (const float*)d_in[5];  // [64,33]
    const float* b2   = (const float*)d_in[6];  // [33]
    float* out = (float*)d_out;

    static int inited = 0;
    if (!inited) {
        cudaFuncSetAttribute(render_kernel,
                             cudaFuncAttributeMaxDynamicSharedMemorySize, SM_TOTAL);
        inited = 1;
    }

    dim3 tb(32, 8);
    dim3 tg(HW / 32, N_BATCH * 3);
    transpose_kernel<<<tg, tb>>>(vol);

    render_kernel<<<NRAYS / RPB, THREADS, SM_TOTAL>>>(orig, dirs, w1, b1, w2, b2, out);
}

// round 16
// speedup vs baseline: 1.2422x; 1.1173x over previous
#include <cuda_runtime.h>
#include <cuda_fp16.h>

// Problem constants (fixed by the dataset)
#define N_BATCH 2
#define HW 65536          // 256*256
#define NRAYS 32768       // N_BATCH * 16384
#define RPW 2             // rays per warp
#define RPB 8             // rays per block (4 warps x 2)
#define THREADS 128
#define FPITCH 18         // feats row pitch in u32 (36 halves, 8B-aligned rows)

typedef unsigned long long u64;
typedef unsigned int u32;

// channels-last fp16 copy of the planes: [(n*3+p)][hw][c]
__device__ __half g_planesH[(size_t)N_BATCH * 3 * HW * 32];

// ---- dynamic smem layout (bytes) ----
#define SM_W1U    0        // 1024 u32: w1 half2 [c][jpair]
#define SM_W2U    4096     // 1024 u32: w2 rgb half2 [j][opair]
#define SM_B1S    8192     // 64 f32
#define SM_W2SIG  8448     // 64 f32
#define SM_B2RS   8704     // 32 f32
#define SM_B2SIG  8832     // 1 f32 (+pad to 8848)
#define SM_TAPA   8848     // 4 warps x 32 x 12 int  = 6144
#define SM_TAPW   14992    // 4 warps x 32 x 6 u32   = 3072 (half2 tap weights)
#define SM_FEATS  18064    // 4 warps x 2 rays x 32*18 u32 = 18432
#define SM_TOTAL  36496

__device__ __forceinline__ __half2 u2h(u32 x) { return *reinterpret_cast<__half2*>(&x); }
__device__ __forceinline__ u32 h2u(__half2 x) { return *reinterpret_cast<u32*>(&x); }
__device__ __forceinline__ float softplus_f(float x) {
    return fmaxf(x, 0.f) + __logf(1.f + __expf(-fabsf(x)));
}

// ---------- kernel 0: [np][C][HW] f32 -> [np][HW][C] fp16 transpose ----------
__global__ void transpose_kernel(const float* __restrict__ in) {
    __shared__ float tile[32][33];
    int np  = blockIdx.y;
    int hw0 = blockIdx.x * 32;
    int tx = threadIdx.x, ty = threadIdx.y;
#pragma unroll
    for (int i = 0; i < 4; i++) {
        int cc = ty * 4 + i;
        tile[cc][tx] = in[(np * 32 + cc) * HW + hw0 + tx];
    }
    __syncthreads();
#pragma unroll
    for (int i = 0; i < 4; i++) {
        int row = ty * 4 + i;
        g_planesH[(size_t)(np * HW + hw0 + row) * 32 + tx] = __float2half(tile[tx][row]);
    }
}

// ---------- kernel 1: renderer, one warp per 2 rays, 4 blocks/SM ----------
__global__ __launch_bounds__(THREADS, 4) void render_kernel(
    const float* __restrict__ orig, const float* __restrict__ dirs,
    const float* __restrict__ w1, const float* __restrict__ b1,
    const float* __restrict__ w2, const float* __restrict__ b2,
    float* __restrict__ out)
{
    extern __shared__ __align__(16) unsigned char smem[];
    u32*   w1u    = (u32*)(smem + SM_W1U);
    u32*   w2u    = (u32*)(smem + SM_W2U);
    float* b1s    = (float*)(smem + SM_B1S);
    float* w2sigs = (float*)(smem + SM_W2SIG);
    float* b2rs   = (float*)(smem + SM_B2RS);
    float* b2sigp = (float*)(smem + SM_B2SIG);
    int*   tapa   = (int*)(smem + SM_TAPA);
    u32*   tapw   = (u32*)(smem + SM_TAPW);
    u32*   featsb = (u32*)(smem + SM_FEATS);   // half2 lattice, pitch FPITCH u32

    const int tid = threadIdx.x;
    for (int i = tid; i < 1024; i += THREADS) {
        int c = i >> 5, jp = i & 31;
        __half2 hv = __floats2half2_rn(w1[c * 64 + 2 * jp], w1[c * 64 + 2 * jp + 1]);
        w1u[i] = h2u(hv);
    }
    for (int i = tid; i < 1024; i += THREADS) {
        int j = i >> 4, op = i & 15;
        __half2 hv = __floats2half2_rn(w2[j * 33 + 1 + 2 * op], w2[j * 33 + 2 + 2 * op]);
        w2u[i] = h2u(hv);
    }
    if (tid < 64) b1s[tid] = b1[tid];
    if (tid < 64) w2sigs[tid] = w2[tid * 33];
    if (tid < 32) b2rs[tid] = b2[tid + 1];
    if (tid == 0) b2sigp[0] = b2[0];
    __syncthreads();

    const int w = tid >> 5, lane = tid & 31;
    const int rg0 = blockIdx.x * RPB + w * RPW;   // first ray of this warp
    const unsigned FULL = 0xffffffffu;

    const float t   = (lane + 0.5f) * 0.03125f;
    const float dep = 2.25f + 1.05f * t;

    // ---- stage 1+2 per ray: taps (lane = sample), then half2 gather ----
#pragma unroll
    for (int r = 0; r < RPW; r++) {
        const int rg = rg0 + r;
        const int n  = rg >> 14;
        const float ox = orig[rg * 3 + 0], oy = orig[rg * 3 + 1], oz = orig[rg * 3 + 2];
        const float dx = dirs[rg * 3 + 0], dy = dirs[rg * 3 + 1], dz = dirs[rg * 3 + 2];
        const float cx = 2.f * fmaf(dep, dx, ox);
        const float cy = 2.f * fmaf(dep, dy, oy);
        const float cz = 2.f * fmaf(dep, dz, oz);

        const int so = w * 32 + lane;   // sample slot for stage-1 writes
#pragma unroll
        for (int p = 0; p < 3; p++) {
            float u = (p == 0) ? cx : (p == 1) ? cy : cx;
            float v = (p == 0) ? cy : (p == 1) ? cz : cz;
            float ix = ((u + 1.f) * 0.5f) * 255.f;
            float iy = ((v + 1.f) * 0.5f) * 255.f;
            float fx0 = floorf(ix), fy0 = floorf(iy);
            // fold the 1/3 plane-mean into the x-weights
            float a0 = (ix - fx0) * (1.f / 3.f);
            float a1 = ((fx0 + 1.f) - ix) * (1.f / 3.f);
            float bb0 = iy - fy0, bb1 = (fy0 + 1.f) - iy;
            int ix0 = (int)fminf(fmaxf(fx0, 0.f), 255.f);
            int ix1 = (int)fminf(fmaxf(fx0 + 1.f, 0.f), 255.f);
            int iy0 = (int)fminf(fmaxf(fy0, 0.f), 255.f);
            int iy1 = (int)fminf(fmaxf(fy0 + 1.f, 0.f), 255.f);
            int base = (n * 3 + p) * (HW * 32);
            int r0 = base + iy0 * (256 * 32);
            int r1 = base + iy1 * (256 * 32);
            *(int4*)&tapa[so * 12 + p * 4] =
                make_int4(r0 + ix0 * 32, r0 + ix1 * 32, r1 + ix0 * 32, r1 + ix1 * 32);
            __half2 hw0 = __floats2half2_rn(a1 * bb1, a0 * bb1);
            __half2 hw1 = __floats2half2_rn(a1 * bb0, a0 * bb0);
            *(uint2*)&tapw[so * 6 + p * 2] = make_uint2(h2u(hw0), h2u(hw1));
        }
        __syncwarp();

        // gather: lanes = 4 channel-octets x 8 samples; each lane privately
        // accumulates its sample's 12 taps for 8 channels in half2 (HFMA2).
        {
            const int q4   = lane & 3;            // channel octet
            const int sub  = lane >> 2;           // sample sub-index (0..7)
            const int cpos = q4 * 8;
            u32* feats = featsb + (w * 2 + r) * (32 * FPITCH);
#pragma unroll 2
            for (int sb = 0; sb < 32; sb += 8) {
                const int s = sb + sub;
                const int* ta = tapa + (w * 32 + s) * 12;
                const u32* tw = tapw + (w * 32 + s) * 6;
                int4 A = *(const int4*)ta;
                int4 B = *(const int4*)(ta + 4);
                int4 C = *(const int4*)(ta + 8);
                uint2 W01 = *(const uint2*)tw;
                uint2 W23 = *(const uint2*)(tw + 2);
                uint2 W45 = *(const uint2*)(tw + 4);
                int addr[12] = {A.x, A.y, A.z, A.w, B.x, B.y, B.z, B.w,
                                C.x, C.y, C.z, C.w};
                u32 wb[6] = {W01.x, W01.y, W23.x, W23.y, W45.x, W45.y};
                __half2 ac0 = __float2half2_rn(0.f);
                __half2 ac1 = ac0, ac2 = ac0, ac3 = ac0;
#pragma unroll
                for (int tp = 0; tp < 12; tp++) {
                    __half2 hp = u2h(wb[tp >> 1]);
                    __half2 wh = (tp & 1) ? __high2half2(hp) : __low2half2(hp);
                    uint4 raw = *(const uint4*)&g_planesH[addr[tp] + cpos];
                    ac0 = __hfma2(wh, u2h(raw.x), ac0);
                    ac1 = __hfma2(wh, u2h(raw.y), ac1);
                    ac2 = __hfma2(wh, u2h(raw.z), ac2);
                    ac3 = __hfma2(wh, u2h(raw.w), ac3);
                }
                uint2* f = (uint2*)(feats + s * FPITCH + q4 * 4);
                f[0] = make_uint2(h2u(ac0), h2u(ac1));
                f[1] = make_uint2(h2u(ac2), h2u(ac3));
            }
        }
        __syncwarp();
    }

    // ---- MLP for both samples (lane's sample of ray0 and ray1), fp16 HFMA2 ----
    uint2 fr0[8], fr1[8];
    {
        const uint2* f0p = (const uint2*)(featsb + (w * 2 + 0) * (32 * FPITCH) + lane * FPITCH);
        const uint2* f1p = (const uint2*)(featsb + (w * 2 + 1) * (32 * FPITCH) + lane * FPITCH);
#pragma unroll
        for (int i = 0; i < 8; i++) { fr0[i] = f0p[i]; fr1[i] = f1p[i]; }
    }

    const float b2sig = b2sigp[0];
    float sig0 = b2sig, sig1 = b2sig;
    __half2 a20h[16], a21h[16];
    const __half2 hz = __float2half2_rn(0.f);
#pragma unroll
    for (int k = 0; k < 16; k++) { a20h[k] = hz; a21h[k] = hz; }

    const uint4* w1q = (const uint4*)w1u;   // [c*8 + q*2 + i]
    const uint4* w2q = (const uint4*)w2u;   // [j*4 + kq]

#pragma unroll
    for (int q = 0; q < 4; q++) {       // 16 hidden units per quarter
        __half2 ac0[8], ac1[8];
#pragma unroll
        for (int jp = 0; jp < 8; jp++) { ac0[jp] = hz; ac1[jp] = hz; }

#pragma unroll
        for (int cu = 0; cu < 8; cu++) {       // uint2 = 4 channels
            u32 p0[2] = {fr0[cu].x, fr0[cu].y};
            u32 p1[2] = {fr1[cu].x, fr1[cu].y};
#pragma unroll
            for (int h2i = 0; h2i < 2; h2i++) {
                __half2 fp0 = u2h(p0[h2i]);
                __half2 fp1 = u2h(p1[h2i]);
#pragma unroll
                for (int e = 0; e < 2; e++) {
                    int c = cu * 4 + h2i * 2 + e;
                    __half2 fd0 = e ? __high2half2(fp0) : __low2half2(fp0);
                    __half2 fd1 = e ? __high2half2(fp1) : __low2half2(fp1);
                    uint4 W0 = w1q[c * 8 + q * 2];
                    uint4 W1 = w1q[c * 8 + q * 2 + 1];
                    ac0[0] = __hfma2(fd0, u2h(W0.x), ac0[0]);
                    ac0[1] = __hfma2(fd0, u2h(W0.y), ac0[1]);
                    ac0[2] = __hfma2(fd0, u2h(W0.z), ac0[2]);
                    ac0[3] = __hfma2(fd0, u2h(W0.w), ac0[3]);
                    ac0[4] = __hfma2(fd0, u2h(W1.x), ac0[4]);
                    ac0[5] = __hfma2(fd0, u2h(W1.y), ac0[5]);
                    ac0[6] = __hfma2(fd0, u2h(W1.z), ac0[6]);
                    ac0[7] = __hfma2(fd0, u2h(W1.w), ac0[7]);
                    ac1[0] = __hfma2(fd1, u2h(W0.x), ac1[0]);
                    ac1[1] = __hfma2(fd1, u2h(W0.y), ac1[1]);
                    ac1[2] = __hfma2(fd1, u2h(W0.z), ac1[2]);
                    ac1[3] = __hfma2(fd1, u2h(W0.w), ac1[3]);
                    ac1[4] = __hfma2(fd1, u2h(W1.x), ac1[4]);
                    ac1[5] = __hfma2(fd1, u2h(W1.y), ac1[5]);
                    ac1[6] = __hfma2(fd1, u2h(W1.z), ac1[6]);
                    ac1[7] = __hfma2(fd1, u2h(W1.w), ac1[7]);
                }
            }
        }
        // consume the 16 hidden units of this quarter into layer 2
#pragma unroll
        for (int jp = 0; jp < 8; jp++) {
            int j0 = q * 16 + 2 * jp;
            float2 hv0 = __half22float2(ac0[jp]);
            float2 hv1 = __half22float2(ac1[jp]);
            float bb0 = b1s[j0], bb1 = b1s[j0 + 1];
            float h00 = softplus_f(hv0.x + bb0), h01 = softplus_f(hv0.y + bb1);
            float h10 = softplus_f(hv1.x + bb0), h11 = softplus_f(hv1.y + bb1);
            float ws0 = w2sigs[j0], ws1 = w2sigs[j0 + 1];
            sig0 = fmaf(h00, ws0, sig0); sig0 = fmaf(h01, ws1, sig0);
            sig1 = fmaf(h10, ws0, sig1); sig1 = fmaf(h11, ws1, sig1);
            __half2 d00 = __float2half2_rn(h00), d01 = __float2half2_rn(h01);
            __half2 d10 = __float2half2_rn(h10), d11 = __float2half2_rn(h11);
#pragma unroll
            for (int kq = 0; kq < 4; kq++) {
                uint4 A = w2q[j0 * 4 + kq];
                uint4 B = w2q[(j0 + 1) * 4 + kq];
                a20h[kq * 4 + 0] = __hfma2(d01, u2h(B.x), __hfma2(d00, u2h(A.x), a20h[kq * 4 + 0]));
                a20h[kq * 4 + 1] = __hfma2(d01, u2h(B.y), __hfma2(d00, u2h(A.y), a20h[kq * 4 + 1]));
                a20h[kq * 4 + 2] = __hfma2(d01, u2h(B.z), __hfma2(d00, u2h(A.z), a20h[kq * 4 + 2]));
                a20h[kq * 4 + 3] = __hfma2(d01, u2h(B.w), __hfma2(d00, u2h(A.w), a20h[kq * 4 + 3]));
                a21h[kq * 4 + 0] = __hfma2(d11, u2h(B.x), __hfma2(d10, u2h(A.x), a21h[kq * 4 + 0]));
                a21h[kq * 4 + 1] = __hfma2(d11, u2h(B.y), __hfma2(d10, u2h(A.y), a21h[kq * 4 + 1]));
                a21h[kq * 4 + 2] = __hfma2(d11, u2h(B.z), __hfma2(d10, u2h(A.z), a21h[kq * 4 + 2]));
                a21h[kq * 4 + 3] = __hfma2(d11, u2h(B.w), __hfma2(d10, u2h(A.w), a21h[kq * 4 + 3]));
            }
        }
    }

    // ---- ray marching per ray: warp scan over samples (lane = s) ----
    const float2* b2p = (const float2*)b2rs;
#pragma unroll
    for (int r = 0; r < RPW; r++) {
        float sig = (r == 0) ? sig0 : sig1;
        float rgb[32];
#pragma unroll
        for (int k = 0; k < 16; k++) {
            float2 o = __half22float2((r == 0) ? a20h[k] : a21h[k]);
            float2 bb = b2p[k];
            rgb[2 * k]     = __fdividef(1.002f, 1.f + __expf(-(o.x + bb.x))) - 0.001f;
            rgb[2 * k + 1] = __fdividef(1.002f, 1.f + __expf(-(o.y + bb.y))) - 0.001f;
        }

        float sig_n = __shfl_down_sync(FULL, sig, 1);
        float dep_n = __shfl_down_sync(FULL, dep, 1);
        float alpha;
        if (lane < 31) {
            float delta = dep_n - dep;
            float dm = 0.5f * (sig + sig_n);
            float dens = softplus_f(dm - 1.f);
            alpha = 1.f - __expf(-delta * dens);
        } else {
            alpha = 0.f;
        }
        float gg = 1.f - alpha + 1e-10f;
        float pscan = gg;
#pragma unroll
        for (int off = 1; off < 32; off <<= 1) {
            float v = __shfl_up_sync(FULL, pscan, off);
            if (lane >= off) pscan *= v;
        }
        float T = __shfl_up_sync(FULL, pscan, 1);
        if (lane == 0) T = 1.f;
        float wgt = alpha * T;
        float wprev = __shfl_up_sync(FULL, wgt, 1);
        if (lane == 0) wprev = 0.f;
        float coeff = 0.5f * (wgt + wprev);

#pragma unroll
        for (int k = 0; k < 32; k++) rgb[k] *= coeff;
#pragma unroll
        for (int off = 16; off >= 1; off >>= 1) {
#pragma unroll
            for (int k = 0; k < 32; k++) rgb[k] += __shfl_xor_sync(FULL, rgb[k], off);
        }
        if (lane == 0) {
            float4* o4 = (float4*)(out + (rg0 + r) * 32);
#pragma unroll
            for (int k = 0; k < 8; k++)
                o4[k] = make_float4(rgb[4 * k], rgb[4 * k + 1], rgb[4 * k + 2], rgb[4 * k + 3]);
        }
    }
}

extern "C" void kernel_launch(void* const* d_in, const int* in_sizes, int n_in,
                              void* d_out, int out_size) {
    const float* vol  = (const float*)d_in[0];  // [2,3,32,256,256]
    const float* orig = (const float*)d_in[1];  // [2,16384,3]
    const float* dirs = (const float*)d_in[2];  // [2,16384,3]
    const float* w1   = (const float*)d_in[3];  // [32,64]
    const float* b1   = (const float*)d_in[4];  // [64]
    const float* w2   = (const float*)d_in[5];  // [64,33]
    const float* b2   = (const float*)d_in[6];  // [33]
    float* out = (float*)d_out;

    static int inited = 0;
    if (!inited) {
        cudaFuncSetAttribute(render_kernel,
                             cudaFuncAttributeMaxDynamicSharedMemorySize, SM_TOTAL);
        inited = 1;
    }

    dim3 tb(32, 8);
    dim3 tg(HW / 32, N_BATCH * 3);
    transpose_kernel<<<tg, tb>>>(vol);

    render_kernel<<<NRAYS / RPB, THREADS, SM_TOTAL>>>(orig, dirs, w1, b1, w2, b2, out);
}

// round 17
// speedup vs baseline: 1.2588x; 1.0134x over previous
#include <cuda_runtime.h>
#include <cuda_fp16.h>

// Problem constants (fixed by the dataset)
#define N_BATCH 2
#define HW 65536          // 256*256
#define NRAYS 32768       // N_BATCH * 16384
#define RPW 2             // rays per warp
#define RPB 8             // rays per block (4 warps x 2)
#define THREADS 128
#define FPITCH 18         // feats row pitch in u32 (36 halves, 8B-aligned rows)

typedef unsigned long long u64;
typedef unsigned int u32;

// channels-last fp16 copy of the planes: [(n*3+p)][hw][c]
__device__ __half g_planesH[(size_t)N_BATCH * 3 * HW * 32];

// ---- dynamic smem layout (bytes) ----
#define SM_W1U    0        // 1024 u32: w1 half2 [c][jpair]
#define SM_W2U    4096     // 1024 u32: w2 rgb half2 [j][opair]
#define SM_B1S    8192     // 64 f32
#define SM_W2SIG  8448     // 64 f32
#define SM_B2RS   8704     // 32 f32
#define SM_B2SIG  8832     // 1 f32 (+pad to 8848)
#define SM_TAPA   8848     // 2 rays x 4 warps x 32 x 12 int = 12288
#define SM_TAPW   21136    // 2 rays x 4 warps x 32 x 6 u32  = 6144
#define SM_FEATS  27280    // 4 warps x 2 rays x 32*18 u32 = 18432
#define SM_TOTAL  45712

__device__ __forceinline__ __half2 u2h(u32 x) { return *reinterpret_cast<__half2*>(&x); }
__device__ __forceinline__ u32 h2u(__half2 x) { return *reinterpret_cast<u32*>(&x); }
__device__ __forceinline__ float softplus_f(float x) {
    return fmaxf(x, 0.f) + __logf(1.f + __expf(-fabsf(x)));
}

// ---------- kernel 0: [np][C][HW] f32 -> [np][HW][C] fp16 transpose ----------
__global__ void transpose_kernel(const float* __restrict__ in) {
    __shared__ float tile[32][33];
    int np  = blockIdx.y;
    int hw0 = blockIdx.x * 32;
    int tx = threadIdx.x, ty = threadIdx.y;
#pragma unroll
    for (int i = 0; i < 4; i++) {
        int cc = ty * 4 + i;
        tile[cc][tx] = in[(np * 32 + cc) * HW + hw0 + tx];
    }
    __syncthreads();
#pragma unroll
    for (int i = 0; i < 4; i++) {
        int row = ty * 4 + i;
        g_planesH[(size_t)(np * HW + hw0 + row) * 32 + tx] = __float2half(tile[tx][row]);
    }
}

// ---------- kernel 1: renderer, one warp per 2 rays, 4 blocks/SM ----------
__global__ __launch_bounds__(THREADS, 4) void render_kernel(
    const float* __restrict__ orig, const float* __restrict__ dirs,
    const float* __restrict__ w1, const float* __restrict__ b1,
    const float* __restrict__ w2, const float* __restrict__ b2,
    float* __restrict__ out)
{
    extern __shared__ __align__(16) unsigned char smem[];
    u32*   w1u    = (u32*)(smem + SM_W1U);
    u32*   w2u    = (u32*)(smem + SM_W2U);
    float* b1s    = (float*)(smem + SM_B1S);
    float* w2sigs = (float*)(smem + SM_W2SIG);
    float* b2rs   = (float*)(smem + SM_B2RS);
    float* b2sigp = (float*)(smem + SM_B2SIG);
    int*   tapa   = (int*)(smem + SM_TAPA);
    u32*   tapw   = (u32*)(smem + SM_TAPW);
    u32*   featsb = (u32*)(smem + SM_FEATS);   // half2 lattice, pitch FPITCH u32

    const int tid = threadIdx.x;
    for (int i = tid; i < 1024; i += THREADS) {
        int c = i >> 5, jp = i & 31;
        __half2 hv = __floats2half2_rn(w1[c * 64 + 2 * jp], w1[c * 64 + 2 * jp + 1]);
        w1u[i] = h2u(hv);
    }
    for (int i = tid; i < 1024; i += THREADS) {
        int j = i >> 4, op = i & 15;
        __half2 hv = __floats2half2_rn(w2[j * 33 + 1 + 2 * op], w2[j * 33 + 2 + 2 * op]);
        w2u[i] = h2u(hv);
    }
    if (tid < 64) b1s[tid] = b1[tid];
    if (tid < 64) w2sigs[tid] = w2[tid * 33];
    if (tid < 32) b2rs[tid] = b2[tid + 1];
    if (tid == 0) b2sigp[0] = b2[0];
    __syncthreads();

    const int w = tid >> 5, lane = tid & 31;
    const int rg0 = blockIdx.x * RPB + w * RPW;   // first ray of this warp
    const unsigned FULL = 0xffffffffu;

    const float t   = (lane + 0.5f) * 0.03125f;
    const float dep = 2.25f + 1.05f * t;

    // ---- stage 1: taps for BOTH rays (lane = sample), no intervening barrier ----
#pragma unroll
    for (int r = 0; r < RPW; r++) {
        const int rg = rg0 + r;
        const int n  = rg >> 14;
        const float ox = orig[rg * 3 + 0], oy = orig[rg * 3 + 1], oz = orig[rg * 3 + 2];
        const float dx = dirs[rg * 3 + 0], dy = dirs[rg * 3 + 1], dz = dirs[rg * 3 + 2];
        const float cx = 2.f * fmaf(dep, dx, ox);
        const float cy = 2.f * fmaf(dep, dy, oy);
        const float cz = 2.f * fmaf(dep, dz, oz);

        int* tar  = tapa + r * (4 * 32 * 12);
        u32* twr  = tapw + r * (4 * 32 * 6);
        const int so = w * 32 + lane;   // sample slot for stage-1 writes
#pragma unroll
        for (int p = 0; p < 3; p++) {
            float u = (p == 0) ? cx : (p == 1) ? cy : cx;
            float v = (p == 0) ? cy : (p == 1) ? cz : cz;
            float ix = ((u + 1.f) * 0.5f) * 255.f;
            float iy = ((v + 1.f) * 0.5f) * 255.f;
            float fx0 = floorf(ix), fy0 = floorf(iy);
            // fold the 1/3 plane-mean into the x-weights
            float a0 = (ix - fx0) * (1.f / 3.f);
            float a1 = ((fx0 + 1.f) - ix) * (1.f / 3.f);
            float bb0 = iy - fy0, bb1 = (fy0 + 1.f) - iy;
            int ix0 = (int)fminf(fmaxf(fx0, 0.f), 255.f);
            int ix1 = (int)fminf(fmaxf(fx0 + 1.f, 0.f), 255.f);
            int iy0 = (int)fminf(fmaxf(fy0, 0.f), 255.f);
            int iy1 = (int)fminf(fmaxf(fy0 + 1.f, 0.f), 255.f);
            int base = (n * 3 + p) * (HW * 32);
            int r0 = base + iy0 * (256 * 32);
            int r1 = base + iy1 * (256 * 32);
            *(int4*)&tar[so * 12 + p * 4] =
                make_int4(r0 + ix0 * 32, r0 + ix1 * 32, r1 + ix0 * 32, r1 + ix1 * 32);
            __half2 hw0 = __floats2half2_rn(a1 * bb1, a0 * bb1);
            __half2 hw1 = __floats2half2_rn(a1 * bb0, a0 * bb0);
            *(uint2*)&twr[so * 6 + p * 2] = make_uint2(h2u(hw0), h2u(hw1));
        }
    }
    __syncwarp();

    // ---- stage 2: gathers for BOTH rays as one uninterrupted LDG stream ----
    {
        const int q4   = lane & 3;            // channel octet
        const int sub  = lane >> 2;           // sample sub-index (0..7)
        const int cpos = q4 * 8;
#pragma unroll
        for (int r = 0; r < RPW; r++) {
            const int* tar = tapa + r * (4 * 32 * 12);
            const u32* twr = tapw + r * (4 * 32 * 6);
            u32* feats = featsb + (w * 2 + r) * (32 * FPITCH);
#pragma unroll 2
            for (int sb = 0; sb < 32; sb += 8) {
                const int s = sb + sub;
                const int* ta = tar + (w * 32 + s) * 12;
                const u32* tw = twr + (w * 32 + s) * 6;
                int4 A = *(const int4*)ta;
                int4 B = *(const int4*)(ta + 4);
                int4 C = *(const int4*)(ta + 8);
                uint2 W01 = *(const uint2*)tw;
                uint2 W23 = *(const uint2*)(tw + 2);
                uint2 W45 = *(const uint2*)(tw + 4);
                int addr[12] = {A.x, A.y, A.z, A.w, B.x, B.y, B.z, B.w,
                                C.x, C.y, C.z, C.w};
                u32 wb[6] = {W01.x, W01.y, W23.x, W23.y, W45.x, W45.y};
                __half2 ac0 = __float2half2_rn(0.f);
                __half2 ac1 = ac0, ac2 = ac0, ac3 = ac0;
#pragma unroll
                for (int tp = 0; tp < 12; tp++) {
                    __half2 hp = u2h(wb[tp >> 1]);
                    __half2 wh = (tp & 1) ? __high2half2(hp) : __low2half2(hp);
                    uint4 raw = *(const uint4*)&g_planesH[addr[tp] + cpos];
                    ac0 = __hfma2(wh, u2h(raw.x), ac0);
                    ac1 = __hfma2(wh, u2h(raw.y), ac1);
                    ac2 = __hfma2(wh, u2h(raw.z), ac2);
                    ac3 = __hfma2(wh, u2h(raw.w), ac3);
                }
                uint2* f = (uint2*)(feats + s * FPITCH + q4 * 4);
                f[0] = make_uint2(h2u(ac0), h2u(ac1));
                f[1] = make_uint2(h2u(ac2), h2u(ac3));
            }
        }
    }
    __syncwarp();

    // ---- MLP for both samples (lane's sample of ray0 and ray1), fp16 HFMA2 ----
    uint2 fr0[8], fr1[8];
    {
        const uint2* f0p = (const uint2*)(featsb + (w * 2 + 0) * (32 * FPITCH) + lane * FPITCH);
        const uint2* f1p = (const uint2*)(featsb + (w * 2 + 1) * (32 * FPITCH) + lane * FPITCH);
#pragma unroll
        for (int i = 0; i < 8; i++) { fr0[i] = f0p[i]; fr1[i] = f1p[i]; }
    }

    const float b2sig = b2sigp[0];
    float sig0 = b2sig, sig1 = b2sig;
    __half2 a20h[16], a21h[16];
    const __half2 hz = __float2half2_rn(0.f);
#pragma unroll
    for (int k = 0; k < 16; k++) { a20h[k] = hz; a21h[k] = hz; }

    const uint4* w1q = (const uint4*)w1u;   // [c*8 + q*2 + i]
    const uint4* w2q = (const uint4*)w2u;   // [j*4 + kq]

#pragma unroll
    for (int q = 0; q < 4; q++) {       // 16 hidden units per quarter
        __half2 ac0[8], ac1[8];
#pragma unroll
        for (int jp = 0; jp < 8; jp++) { ac0[jp] = hz; ac1[jp] = hz; }

#pragma unroll
        for (int cu = 0; cu < 8; cu++) {       // uint2 = 4 channels
            u32 p0[2] = {fr0[cu].x, fr0[cu].y};
            u32 p1[2] = {fr1[cu].x, fr1[cu].y};
#pragma unroll
            for (int h2i = 0; h2i < 2; h2i++) {
                __half2 fp0 = u2h(p0[h2i]);
                __half2 fp1 = u2h(p1[h2i]);
#pragma unroll
                for (int e = 0; e < 2; e++) {
                    int c = cu * 4 + h2i * 2 + e;
                    __half2 fd0 = e ? __high2half2(fp0) : __low2half2(fp0);
                    __half2 fd1 = e ? __high2half2(fp1) : __low2half2(fp1);
                    uint4 W0 = w1q[c * 8 + q * 2];
                    uint4 W1 = w1q[c * 8 + q * 2 + 1];
                    ac0[0] = __hfma2(fd0, u2h(W0.x), ac0[0]);
                    ac0[1] = __hfma2(fd0, u2h(W0.y), ac0[1]);
                    ac0[2] = __hfma2(fd0, u2h(W0.z), ac0[2]);
                    ac0[3] = __hfma2(fd0, u2h(W0.w), ac0[3]);
                    ac0[4] = __hfma2(fd0, u2h(W1.x), ac0[4]);
                    ac0[5] = __hfma2(fd0, u2h(W1.y), ac0[5]);
                    ac0[6] = __hfma2(fd0, u2h(W1.z), ac0[6]);
                    ac0[7] = __hfma2(fd0, u2h(W1.w), ac0[7]);
                    ac1[0] = __hfma2(fd1, u2h(W0.x), ac1[0]);
                    ac1[1] = __hfma2(fd1, u2h(W0.y), ac1[1]);
                    ac1[2] = __hfma2(fd1, u2h(W0.z), ac1[2]);
                    ac1[3] = __hfma2(fd1, u2h(W0.w), ac1[3]);
                    ac1[4] = __hfma2(fd1, u2h(W1.x), ac1[4]);
                    ac1[5] = __hfma2(fd1, u2h(W1.y), ac1[5]);
                    ac1[6] = __hfma2(fd1, u2h(W1.z), ac1[6]);
                    ac1[7] = __hfma2(fd1, u2h(W1.w), ac1[7]);
                }
            }
        }
        // consume the 16 hidden units of this quarter into layer 2
#pragma unroll
        for (int jp = 0; jp < 8; jp++) {
            int j0 = q * 16 + 2 * jp;
            float2 hv0 = __half22float2(ac0[jp]);
            float2 hv1 = __half22float2(ac1[jp]);
            float bb0 = b1s[j0], bb1 = b1s[j0 + 1];
            float h00 = softplus_f(hv0.x + bb0), h01 = softplus_f(hv0.y + bb1);
            float h10 = softplus_f(hv1.x + bb0), h11 = softplus_f(hv1.y + bb1);
            float ws0 = w2sigs[j0], ws1 = w2sigs[j0 + 1];
            sig0 = fmaf(h00, ws0, sig0); sig0 = fmaf(h01, ws1, sig0);
            sig1 = fmaf(h10, ws0, sig1); sig1 = fmaf(h11, ws1, sig1);
            __half2 d00 = __float2half2_rn(h00), d01 = __float2half2_rn(h01);
            __half2 d10 = __float2half2_rn(h10), d11 = __float2half2_rn(h11);
#pragma unroll
            for (int kq = 0; kq < 4; kq++) {
                uint4 A = w2q[j0 * 4 + kq];
                uint4 B = w2q[(j0 + 1) * 4 + kq];
                a20h[kq * 4 + 0] = __hfma2(d01, u2h(B.x), __hfma2(d00, u2h(A.x), a20h[kq * 4 + 0]));
                a20h[kq * 4 + 1] = __hfma2(d01, u2h(B.y), __hfma2(d00, u2h(A.y), a20h[kq * 4 + 1]));
                a20h[kq * 4 + 2] = __hfma2(d01, u2h(B.z), __hfma2(d00, u2h(A.z), a20h[kq * 4 + 2]));
                a20h[kq * 4 + 3] = __hfma2(d01, u2h(B.w), __hfma2(d00, u2h(A.w), a20h[kq * 4 + 3]));
                a21h[kq * 4 + 0] = __hfma2(d11, u2h(B.x), __hfma2(d10, u2h(A.x), a21h[kq * 4 + 0]));
                a21h[kq * 4 + 1] = __hfma2(d11, u2h(B.y), __hfma2(d10, u2h(A.y), a21h[kq * 4 + 1]));
                a21h[kq * 4 + 2] = __hfma2(d11, u2h(B.z), __hfma2(d10, u2h(A.z), a21h[kq * 4 + 2]));
                a21h[kq * 4 + 3] = __hfma2(d11, u2h(B.w), __hfma2(d10, u2h(A.w), a21h[kq * 4 + 3]));
            }
        }
    }

    // ---- ray marching per ray: warp scan over samples (lane = s) ----
    const float2* b2p = (const float2*)b2rs;
#pragma unroll
    for (int r = 0; r < RPW; r++) {
        float sig = (r == 0) ? sig0 : sig1;
        float rgb[32];
#pragma unroll
        for (int k = 0; k < 16; k++) {
            float2 o = __half22float2((r == 0) ? a20h[k] : a21h[k]);
            float2 bb = b2p[k];
            rgb[2 * k]     = __fdividef(1.002f, 1.f + __expf(-(o.x + bb.x))) - 0.001f;
            rgb[2 * k + 1] = __fdividef(1.002f, 1.f + __expf(-(o.y + bb.y))) - 0.001f;
        }

        float sig_n = __shfl_down_sync(FULL, sig, 1);
        float dep_n = __shfl_down_sync(FULL, dep, 1);
        float alpha;
        if (lane < 31) {
            float delta = dep_n - dep;
            float dm = 0.5f * (sig + sig_n);
            float dens = softplus_f(dm - 1.f);
            alpha = 1.f - __expf(-delta * dens);
        } else {
            alpha = 0.f;
        }
        float gg = 1.f - alpha + 1e-10f;
        float pscan = gg;
#pragma unroll
        for (int off = 1; off < 32; off <<= 1) {
            float v = __shfl_up_sync(FULL, pscan, off);
            if (lane >= off) pscan *= v;
        }
        float T = __shfl_up_sync(FULL, pscan, 1);
        if (lane == 0) T = 1.f;
        float wgt = alpha * T;
        float wprev = __shfl_up_sync(FULL, wgt, 1);
        if (lane == 0) wprev = 0.f;
        float coeff = 0.5f * (wgt + wprev);

#pragma unroll
        for (int k = 0; k < 32; k++) rgb[k] *= coeff;
#pragma unroll
        for (int off = 16; off >= 1; off >>= 1) {
#pragma unroll
            for (int k = 0; k < 32; k++) rgb[k] += __shfl_xor_sync(FULL, rgb[k], off);
        }
        if (lane == 0) {
            float4* o4 = (float4*)(out + (rg0 + r) * 32);
#pragma unroll
            for (int k = 0; k < 8; k++)
                o4[k] = make_float4(rgb[4 * k], rgb[4 * k + 1], rgb[4 * k + 2], rgb[4 * k + 3]);
        }
    }
}

extern "C" void kernel_launch(void* const* d_in, const int* in_sizes, int n_in,
                              void* d_out, int out_size) {
    const float* vol  = (const float*)d_in[0];  // [2,3,32,256,256]
    const float* orig = (const float*)d_in[1];  // [2,16384,3]
    const float* dirs = (const float*)d_in[2];  // [2,16384,3]
    const float* w1   = (const float*)d_in[3];  // [32,64]
    const float* b1   = (const float*)d_in[4];  // [64]
    const float* w2   = (const float*)d_in[5];  // [64,33]
    const float* b2   = (const float*)d_in[6];  // [33]
    float* out = (float*)d_out;

    static int inited = 0;
    if (!inited) {
        cudaFuncSetAttribute(render_kernel,
                             cudaFuncAttributeMaxDynamicSharedMemorySize, SM_TOTAL);
        inited = 1;
    }

    dim3 tb(32, 8);
    dim3 tg(HW / 32, N_BATCH * 3);
    transpose_kernel<<<tg, tb>>>(vol);

    render_kernel<<<NRAYS / RPB, THREADS, SM_TOTAL>>>(orig, dirs, w1, b1, w2, b2, out);
}